// round 6
// baseline (speedup 1.0000x reference)
#include <cuda_runtime.h>
#include <cuda_bf16.h>

// Problem shape (fixed by the dataset): image (2048, 8192, 4) fp32 -> points (2048*8192, 3) fp32
#define H 2048
#define W 8192
#define NPIX (H * W)
#define PIX_PER_THREAD 4
#define NQUADS (NPIX / PIX_PER_THREAD)     // 4,194,304 thread-quads
#define BLOCK 256
#define SMS 152                            // GB300 SM count
#define CTAS_PER_SM 8
#define GRID (SMS * CTAS_PER_SM)           // persistent single-wave grid

// Precomputed per-column / per-row trig tables (device globals: allocation-free scratch)
__device__ __align__(16) float g_cy[W];   // cos(yaw_j)
__device__ __align__(16) float g_sy[W];   // -sin(yaw_j)  (minus folded in)
__device__ __align__(16) float g_sp[H];   // sin(pitch_i)

__global__ void build_tables_kernel() {
    int idx = blockIdx.x * blockDim.x + threadIdx.x;
    const float PI = 3.14159265358979323846f;
    const float FOV_DOWN_ABS = 15.0f / 180.0f * PI;           // |fov_down|
    const float FOV_SPAN     = 30.0f / 180.0f * PI;           // fov_up + |fov_down|
    if (idx < W) {
        float yaw = (float)idx * (2.0f * PI / (float)W) - PI;
        float s, c;
        sincosf(yaw, &s, &c);
        g_cy[idx] = c;
        g_sy[idx] = -s;
    }
    if (idx < H) {
        float pitch = (1.0f - (float)idx * (1.0f / (float)H)) * FOV_SPAN - FOV_DOWN_ABS;
        g_sp[idx] = sinf(pitch);
    }
}

__global__ void __launch_bounds__(BLOCK)
project_kernel(const float4* __restrict__ im, float4* __restrict__ out) {
    const float4* __restrict__ cy4 = reinterpret_cast<const float4*>(g_cy);
    const float4* __restrict__ sy4 = reinterpret_cast<const float4*>(g_sy);

    const int stride = GRID * BLOCK;
    for (int t = blockIdx.x * BLOCK + threadIdx.x; t < NQUADS; t += stride) {
        int p0  = t << 2;          // first pixel of this quad
        int row = p0 >> 13;        // / W  (W = 8192)
        int c4  = t & 2047;        // float4 index into column tables

        float  sp = g_sp[row];
        float4 cy = __ldg(cy4 + c4);
        float4 sy = __ldg(sy4 + c4);

        // 4 consecutive pixels, depth is the .w channel (streaming loads)
        float4 v0 = __ldcs(im + p0 + 0);
        float4 v1 = __ldcs(im + p0 + 1);
        float4 v2 = __ldcs(im + p0 + 2);
        float4 v3 = __ldcs(im + p0 + 3);
        float d0 = v0.w, d1 = v1.w, d2 = v2.w, d3 = v3.w;

        float x0 = d0 * cy.x, y0 = d0 * sy.x, z0 = d0 * sp;
        float x1 = d1 * cy.y, y1 = d1 * sy.y, z1 = d1 * sp;
        float x2 = d2 * cy.z, y2 = d2 * sy.z, z2 = d2 * sp;
        float x3 = d3 * cy.w, y3 = d3 * sy.w, z3 = d3 * sp;

        // 12 contiguous output floats -> 3 dense float4 streaming stores
        int ob = 3 * t;
        __stcs(out + ob + 0, make_float4(x0, y0, z0, x1));
        __stcs(out + ob + 1, make_float4(y1, z1, x2, y2));
        __stcs(out + ob + 2, make_float4(z2, x3, y3, z3));
    }
}

extern "C" void kernel_launch(void* const* d_in, const int* in_sizes, int n_in,
                              void* d_out, int out_size) {
    (void)in_sizes; (void)n_in; (void)out_size;
    const float4* im = (const float4*)d_in[0];
    float4* out = (float4*)d_out;

    // Tiny prologue: fill trig tables (float precision, ~10K sincosf)
    build_tables_kernel<<<(W + 255) / 256, 256>>>();

    // Persistent single-wave streaming kernel
    project_kernel<<<GRID, BLOCK>>>(im, out);
}

// round 8
// speedup vs baseline: 1.2430x; 1.2430x over previous
#include <cuda_runtime.h>
#include <cuda_bf16.h>

// Problem shape (fixed by the dataset): image (2048, 8192, 4) fp32 -> points (2048*8192, 3) fp32
#define H 2048
#define W 8192
#define NPIX (H * W)
#define PIX_PER_THREAD 4
#define NTHREADS (NPIX / PIX_PER_THREAD)   // 4,194,304
#define BLOCK 256

// Precomputed per-column / per-row trig tables (device globals: allocation-free scratch)
__device__ __align__(16) float g_cy[W];   // cos(yaw_j)
__device__ __align__(16) float g_sy[W];   // -sin(yaw_j)  (minus folded in)
__device__ __align__(16) float g_sp[H];   // sin(pitch_i)

__global__ void build_tables_kernel() {
    int idx = blockIdx.x * blockDim.x + threadIdx.x;
    const float PI = 3.14159265358979323846f;
    const float FOV_DOWN_ABS = 15.0f / 180.0f * PI;           // |fov_down|
    const float FOV_SPAN     = 30.0f / 180.0f * PI;           // fov_up + |fov_down|
    if (idx < W) {
        float yaw = (float)idx * (2.0f * PI / (float)W) - PI;
        float s, c;
        sincosf(yaw, &s, &c);
        g_cy[idx] = c;
        g_sy[idx] = -s;
    }
    if (idx < H) {
        float pitch = (1.0f - (float)idx * (1.0f / (float)H)) * FOV_SPAN - FOV_DOWN_ABS;
        g_sp[idx] = sinf(pitch);
    }
}

__global__ void __launch_bounds__(BLOCK)
project_kernel(const float4* __restrict__ im, float4* __restrict__ out) {
    int t = blockIdx.x * BLOCK + threadIdx.x;      // 0 .. NTHREADS-1
    int p0 = t << 2;                               // first pixel handled by this thread
    int row = p0 >> 13;                            // / W  (W = 8192)
    int c4  = t & 2047;                            // (p0 & 8191) / 4 : float4 index into tables

    float sp = g_sp[row];
    const float4* __restrict__ cy4 = reinterpret_cast<const float4*>(g_cy);
    const float4* __restrict__ sy4 = reinterpret_cast<const float4*>(g_sy);
    float4 cy = __ldg(cy4 + c4);
    float4 sy = __ldg(sy4 + c4);

    // 4 consecutive pixels, depth is the .w channel
    float4 v0 = im[p0 + 0];
    float4 v1 = im[p0 + 1];
    float4 v2 = im[p0 + 2];
    float4 v3 = im[p0 + 3];
    float d0 = v0.w, d1 = v1.w, d2 = v2.w, d3 = v3.w;

    float x0 = d0 * cy.x, y0 = d0 * sy.x, z0 = d0 * sp;
    float x1 = d1 * cy.y, y1 = d1 * sy.y, z1 = d1 * sp;
    float x2 = d2 * cy.z, y2 = d2 * sy.z, z2 = d2 * sp;
    float x3 = d3 * cy.w, y3 = d3 * sy.w, z3 = d3 * sp;

    // 12 contiguous output floats -> 3 dense float4 stores
    int ob = 3 * t;
    out[ob + 0] = make_float4(x0, y0, z0, x1);
    out[ob + 1] = make_float4(y1, z1, x2, y2);
    out[ob + 2] = make_float4(z2, x3, y3, z3);
}

extern "C" void kernel_launch(void* const* d_in, const int* in_sizes, int n_in,
                              void* d_out, int out_size) {
    (void)in_sizes; (void)n_in; (void)out_size;
    const float4* im = (const float4*)d_in[0];
    float4* out = (float4*)d_out;

    // Tiny prologue: fill trig tables (float precision, ~10K sincosf)
    build_tables_kernel<<<(W + 255) / 256, 256>>>();

    // Main streaming kernel: 4,194,304 threads, 4 pixels each, one wave-rich flat launch
    project_kernel<<<NTHREADS / BLOCK, BLOCK>>>(im, out);
}